// round 4
// baseline (speedup 1.0000x reference)
#include <cuda_runtime.h>
#include <math.h>

#define BB 4
#define TT 2048
#define CC 1024
#define HH 16
#define HD 64
#define MM (BB*TT)

// Scratch (static device arrays; cudaMalloc is forbidden).
__device__ float g_Q[BB*HH*TT*HD];   // [b,h,t,d], Q pre-scaled by 1/sqrt(hd)
__device__ float g_K[BB*HH*TT*HD];
__device__ float g_V[BB*HH*TT*HD];
__device__ float g_attn[MM*CC];      // [b*t, h*hd] merged heads

// packed f32x2 helpers
#define PACK2(d, s)    asm("mov.b64 %0, {%1, %1};" : "=l"(d) : "f"(s))
#define FMA2(d, a, b)  asm("fma.rn.f32x2 %0, %1, %2, %0;" : "+l"(d) : "l"(a), "l"(b))
#define MUL2(d, s)     asm("mul.rn.f32x2 %0, %0, %1;" : "+l"(d) : "l"(s))
#define UNPK(lo, hi, s) asm("mov.b64 {%0, %1}, %2;" : "=f"(lo), "=f"(hi) : "l"(s))

// ---------------------------------------------------------------------------
// SGEMM: out[m,n] = sum_k A[m,k]*W[n,k] (+bias). 128x128x8 tiles, 256 thr,
// 8x8 micro-tile as 8x4 packed f32x2 pairs, double-buffered smem.
// ---------------------------------------------------------------------------
template<bool IS_QKV, bool USE_GATTN>
__global__ __launch_bounds__(256)
void gemm_kernel(const float* __restrict__ A_in, const float* __restrict__ W,
                 const float* __restrict__ bias, float* __restrict__ out)
{
    __shared__ __align__(16) float sA[2][8][132];
    __shared__ __align__(16) float sB[2][8][132];

    const float* A = USE_GATTN ? g_attn : A_in;

    const int tid = threadIdx.x;
    const int tx4 = (tid & 15) * 4;
    const int ty4 = (tid >> 4) * 4;
    const int m0 = blockIdx.y * 128;
    const int n0 = blockIdx.x * 128;

    // loader: warp covers 16 consecutive rows x 32B -> coalesced gmem,
    // transposed smem stores land on all 32 banks (conflict-free).
    const int lr  = tid >> 1;
    const int lk4 = (tid & 1) * 4;
    const float* Ap = A + (size_t)(m0 + lr) * CC + lk4;
    const float* Wp = W + (size_t)(n0 + lr) * CC + lk4;

    unsigned long long acc[8][4];
    #pragma unroll
    for (int i = 0; i < 8; ++i)
        #pragma unroll
        for (int j = 0; j < 4; ++j) acc[i][j] = 0ull;

    // preload tile 0
    float4 av = *(const float4*)Ap;
    float4 wv = *(const float4*)Wp;
    sA[0][lk4+0][lr]=av.x; sA[0][lk4+1][lr]=av.y; sA[0][lk4+2][lr]=av.z; sA[0][lk4+3][lr]=av.w;
    sB[0][lk4+0][lr]=wv.x; sB[0][lk4+1][lr]=wv.y; sB[0][lk4+2][lr]=wv.z; sB[0][lk4+3][lr]=wv.w;
    __syncthreads();

    int buf = 0;
    #pragma unroll 1
    for (int kt = 1; kt <= 128; ++kt) {
        if (kt < 128) {
            av = *(const float4*)(Ap + kt * 8);
            wv = *(const float4*)(Wp + kt * 8);
        }
        #pragma unroll
        for (int k = 0; k < 8; ++k) {
            float4 a0 = *(const float4*)&sA[buf][k][ty4];
            float4 a1 = *(const float4*)&sA[buf][k][64 + ty4];
            ulonglong2 b0 = *(const ulonglong2*)&sB[buf][k][tx4];
            ulonglong2 b1 = *(const ulonglong2*)&sB[buf][k][64 + tx4];
            float as[8] = {a0.x, a0.y, a0.z, a0.w, a1.x, a1.y, a1.z, a1.w};
            #pragma unroll
            for (int i = 0; i < 8; ++i) {
                unsigned long long ap;
                PACK2(ap, as[i]);
                FMA2(acc[i][0], ap, b0.x);
                FMA2(acc[i][1], ap, b0.y);
                FMA2(acc[i][2], ap, b1.x);
                FMA2(acc[i][3], ap, b1.y);
            }
        }
        if (kt < 128) {
            sA[buf^1][lk4+0][lr]=av.x; sA[buf^1][lk4+1][lr]=av.y;
            sA[buf^1][lk4+2][lr]=av.z; sA[buf^1][lk4+3][lr]=av.w;
            sB[buf^1][lk4+0][lr]=wv.x; sB[buf^1][lk4+1][lr]=wv.y;
            sB[buf^1][lk4+2][lr]=wv.z; sB[buf^1][lk4+3][lr]=wv.w;
            __syncthreads();
        }
        buf ^= 1;
    }

    // epilogue
    #pragma unroll
    for (int i = 0; i < 8; ++i) {
        const int m = m0 + ((i < 4) ? ty4 + i : 64 + ty4 + i - 4);
        #pragma unroll
        for (int jp = 0; jp < 4; ++jp) {
            const int cb = ((jp < 2) ? tx4 + 2*jp : 64 + tx4 + 2*(jp - 2));
            float lo, hi;
            UNPK(lo, hi, acc[i][jp]);
            #pragma unroll
            for (int e = 0; e < 2; ++e) {
                const int n = n0 + cb + e;
                float v = (e ? hi : lo) + bias[n];
                if (IS_QKV) {
                    const int which = n >> 10;      // 0=q 1=k 2=v
                    const int hc = n & 1023;
                    const int h  = hc >> 6;
                    const int d  = hc & 63;
                    const int b  = m >> 11;
                    const int t  = m & (TT - 1);
                    float* dst = (which == 0) ? g_Q : (which == 1) ? g_K : g_V;
                    if (which == 0) v *= 0.125f;    // 1/sqrt(64) folded into Q
                    dst[(size_t)((b*HH + h)*TT + t) * HD + d] = v;
                } else {
                    out[(size_t)m * CC + n] = v;
                }
            }
        }
    }
}

// ---------------------------------------------------------------------------
// Causal flash attention: 64 queries x 64 keys per tile, 128 threads,
// 8x4 micro-tile as 8x2 packed f32x2 pairs. 48KB static smem, 4 CTAs/SM.
// ---------------------------------------------------------------------------
__global__ __launch_bounds__(128)
void attn_kernel()
{
    __shared__ __align__(16) float sQt[64][64];   // [d][r]
    __shared__ __align__(16) float sKV[64][64];   // K: [d][c]; V: [k][dv]
    __shared__ __align__(16) float sP [64][64];   // [r][c]

    const int tid = threadIdx.x;
    const int tx  = tid & 15;
    const int ty  = tid >> 4;                     // 0..7
    const int tx4 = tx * 4, ty4 = ty * 4;
    const int q0 = blockIdx.x * 64;
    const int bh = blockIdx.y;

    const float* Qb = g_Q + (size_t)bh * TT * HD;
    const float* Kb = g_K + (size_t)bh * TT * HD;
    const float* Vb = g_V + (size_t)bh * TT * HD;

    int rIdx[8];
    #pragma unroll
    for (int i = 0; i < 8; ++i) rIdx[i] = (i < 4) ? ty4 + i : 32 + ty4 + (i - 4);

    // Load Q transposed: warp = 16 rows x 32B, conflict-free stores
    {
        const int r = tid >> 1;
        #pragma unroll
        for (int s = 0; s < 8; ++s) {
            const int d4 = ((tid & 1) + 2*s) * 4;
            float4 v = *(const float4*)&Qb[(size_t)(q0 + r) * HD + d4];
            sQt[d4+0][r]=v.x; sQt[d4+1][r]=v.y; sQt[d4+2][r]=v.z; sQt[d4+3][r]=v.w;
        }
    }

    float m_i[8], l_i[8];
    unsigned long long accp[8][2];
    #pragma unroll
    for (int i = 0; i < 8; ++i) {
        m_i[i] = -1e30f; l_i[i] = 0.f;
        accp[i][0] = 0ull; accp[i][1] = 0ull;
    }

    #pragma unroll 1
    for (int j0 = 0; j0 <= q0; j0 += 64) {
        __syncthreads();   // prev PV done with sKV / sP
        // K tile transposed
        {
            const int c = tid >> 1;
            #pragma unroll
            for (int s = 0; s < 8; ++s) {
                const int d4 = ((tid & 1) + 2*s) * 4;
                float4 v = *(const float4*)&Kb[(size_t)(j0 + c) * HD + d4];
                sKV[d4+0][c]=v.x; sKV[d4+1][c]=v.y; sKV[d4+2][c]=v.z; sKV[d4+3][c]=v.w;
            }
        }
        __syncthreads();

        // S = Q K^T (scale folded into Q) -- packed pairs along key cols
        unsigned long long sp[8][2];
        #pragma unroll
        for (int i = 0; i < 8; ++i) { sp[i][0] = 0ull; sp[i][1] = 0ull; }
        #pragma unroll 4
        for (int d = 0; d < 64; ++d) {
            float4 a0 = *(const float4*)&sQt[d][ty4];
            float4 a1 = *(const float4*)&sQt[d][32 + ty4];
            ulonglong2 b = *(const ulonglong2*)&sKV[d][tx4];
            float as[8] = {a0.x, a0.y, a0.z, a0.w, a1.x, a1.y, a1.z, a1.w};
            #pragma unroll
            for (int i = 0; i < 8; ++i) {
                unsigned long long ap;
                PACK2(ap, as[i]);
                FMA2(sp[i][0], ap, b.x);
                FMA2(sp[i][1], ap, b.y);
            }
        }
        float sf[8][4];
        #pragma unroll
        for (int i = 0; i < 8; ++i) {
            UNPK(sf[i][0], sf[i][1], sp[i][0]);
            UNPK(sf[i][2], sf[i][3], sp[i][1]);
        }

        if (j0 + 63 > q0) {  // diagonal tile
            #pragma unroll
            for (int i = 0; i < 8; ++i) {
                const int rg = q0 + rIdx[i];
                #pragma unroll
                for (int j = 0; j < 4; ++j)
                    if (j0 + tx4 + j > rg) sf[i][j] = -1e30f;
            }
        }

        // online softmax
        #pragma unroll
        for (int i = 0; i < 8; ++i) {
            float tm = fmaxf(fmaxf(sf[i][0], sf[i][1]), fmaxf(sf[i][2], sf[i][3]));
            #pragma unroll
            for (int off = 8; off > 0; off >>= 1)
                tm = fmaxf(tm, __shfl_xor_sync(0xffffffffu, tm, off));
            const float mnew = fmaxf(m_i[i], tm);
            const float corr = __expf(m_i[i] - mnew);
            float4 pv;
            pv.x = __expf(sf[i][0] - mnew);
            pv.y = __expf(sf[i][1] - mnew);
            pv.z = __expf(sf[i][2] - mnew);
            pv.w = __expf(sf[i][3] - mnew);
            *(float4*)&sP[rIdx[i]][tx4] = pv;
            float ls = pv.x + pv.y + pv.z + pv.w;
            #pragma unroll
            for (int off = 8; off > 0; off >>= 1)
                ls += __shfl_xor_sync(0xffffffffu, ls, off);
            l_i[i] = l_i[i] * corr + ls;
            m_i[i] = mnew;
            unsigned long long cp;
            PACK2(cp, corr);
            MUL2(accp[i][0], cp);
            MUL2(accp[i][1], cp);
        }
        __syncthreads();   // K reads + P writes complete

        // V tile natural layout
        #pragma unroll
        for (int s = 0; s < 8; ++s) {
            const int f = tid + s * 128;
            const int r = f >> 4, c4 = (f & 15) * 4;
            *(float4*)&sKV[r][c4] = *(const float4*)&Vb[(size_t)(j0 + r) * HD + c4];
        }
        __syncthreads();

        // acc += P V
        #pragma unroll 4
        for (int k = 0; k < 64; ++k) {
            ulonglong2 v = *(const ulonglong2*)&sKV[k][tx4];
            #pragma unroll
            for (int i = 0; i < 8; ++i) {
                unsigned long long pp;
                PACK2(pp, sP[rIdx[i]][k]);
                FMA2(accp[i][0], pp, v.x);
                FMA2(accp[i][1], pp, v.y);
            }
        }
    }

    // epilogue: normalize, merge heads into g_attn [b*t, h*hd]
    const int b = bh >> 4;
    const int h = bh & 15;
    #pragma unroll
    for (int i = 0; i < 8; ++i) {
        const float inv = 1.f / l_i[i];
        const int t = q0 + rIdx[i];
        float4 o;
        UNPK(o.x, o.y, accp[i][0]);
        UNPK(o.z, o.w, accp[i][1]);
        o.x *= inv; o.y *= inv; o.z *= inv; o.w *= inv;
        *(float4*)&g_attn[(size_t)(b*TT + t) * CC + h*HD + tx4] = o;
    }
}

// ---------------------------------------------------------------------------
extern "C" void kernel_launch(void* const* d_in, const int* in_sizes, int n_in,
                              void* d_out, int out_size)
{
    const float* x     = (const float*)d_in[0];
    const float* qkv_w = (const float*)d_in[1];
    const float* qkv_b = (const float*)d_in[2];
    const float* out_w = (const float*)d_in[3];
    const float* out_b = (const float*)d_in[4];
    float* y = (float*)d_out;

    gemm_kernel<true, false><<<dim3(3*CC/128, MM/128), 256>>>(x, qkv_w, qkv_b, nullptr);
    attn_kernel<<<dim3(TT/64, BB*HH), 128>>>();
    gemm_kernel<false, true><<<dim3(CC/128, MM/128), 256>>>(nullptr, out_w, out_b, y);
}

// round 9
// speedup vs baseline: 1.4472x; 1.4472x over previous
#include <cuda_runtime.h>
#include <cuda_bf16.h>
#include <cstdint>
#include <math.h>

#define BB 4
#define TT 2048
#define CC 1024
#define HH 16
#define HD 64
#define MM (BB*TT)

// ---------------- scratch (static device arrays; no cudaMalloc) -------------
__device__ float g_Q[BB*HH*TT*HD];   // [b,h,t,d], Q pre-scaled by 1/8
__device__ float g_K[BB*HH*TT*HD];
__device__ float g_V[BB*HH*TT*HD];
__device__ float g_attn[MM*CC];      // [b*t, h*hd]

__device__ __nv_bfloat16 g_xh[MM*CC],     g_xl[MM*CC];
__device__ __nv_bfloat16 g_wqh[3*CC*CC],  g_wql[3*CC*CC];
__device__ __nv_bfloat16 g_woh[CC*CC],    g_wol[CC*CC];
__device__ __nv_bfloat16 g_ah[MM*CC],     g_al[MM*CC];

// packed f32x2 helpers (attention kernel)
#define PACK2(d, s)    asm("mov.b64 %0, {%1, %1};" : "=l"(d) : "f"(s))
#define FMA2(d, a, b)  asm("fma.rn.f32x2 %0, %1, %2, %0;" : "+l"(d) : "l"(a), "l"(b))
#define MUL2(d, s)     asm("mul.rn.f32x2 %0, %0, %1;" : "+l"(d) : "l"(s))
#define UNPK(lo, hi, s) asm("mov.b64 {%0, %1}, %2;" : "=f"(lo), "=f"(hi) : "l"(s))

// bf16 mma: D(f32) += A(bf16) * B(bf16)
#define MMA_BF16(acc, a, b) \
    asm("mma.sync.aligned.m16n8k16.row.col.f32.bf16.bf16.f32 " \
        "{%0,%1,%2,%3}, {%4,%5,%6,%7}, {%8,%9}, {%0,%1,%2,%3};" \
        : "+f"(acc[0]), "+f"(acc[1]), "+f"(acc[2]), "+f"(acc[3]) \
        : "r"(a[0]), "r"(a[1]), "r"(a[2]), "r"(a[3]), "r"(b[0]), "r"(b[1]))

#define LDSM_X4(r, addr) \
    asm volatile("ldmatrix.sync.aligned.m8n8.x4.shared.b16 {%0,%1,%2,%3}, [%4];" \
        : "=r"((r)[0]), "=r"((r)[1]), "=r"((r)[2]), "=r"((r)[3]) : "r"(addr))
#define LDSM_X2(r, addr) \
    asm volatile("ldmatrix.sync.aligned.m8n8.x2.shared.b16 {%0,%1}, [%2];" \
        : "=r"((r)[0]), "=r"((r)[1]) : "r"(addr))

__device__ __forceinline__ unsigned smem_u32(const void* p) {
    return (unsigned)__cvta_generic_to_shared(p);
}

// ---------------------------------------------------------------------------
// split: fp32 -> (hi, lo) bf16. DST selects destination arrays IN DEVICE CODE
// (passing __device__ symbols as host-side kernel args was the R5-R8 bug).
// DST: 0=x, 1=qkv_w, 2=out_w, 3=attn(g_attn source implicit)
// ---------------------------------------------------------------------------
template<int DST>
__global__ __launch_bounds__(256)
void split_kernel(const float4* __restrict__ src_in, int n4)
{
    int i = blockIdx.x * blockDim.x + threadIdx.x;
    if (i >= n4) return;

    const float4* src = (DST == 3) ? (const float4*)g_attn : src_in;
    ushort4* hi; ushort4* lo;
    if      (DST == 0) { hi = (ushort4*)g_xh;  lo = (ushort4*)g_xl;  }
    else if (DST == 1) { hi = (ushort4*)g_wqh; lo = (ushort4*)g_wql; }
    else if (DST == 2) { hi = (ushort4*)g_woh; lo = (ushort4*)g_wol; }
    else               { hi = (ushort4*)g_ah;  lo = (ushort4*)g_al;  }

    float4 v = src[i];
    ushort4 h, l;
#define SPL(c, hc, lc) { \
        __nv_bfloat16 hb = __float2bfloat16_rn(v.c); \
        __nv_bfloat16 lb = __float2bfloat16_rn(v.c - __bfloat162float(hb)); \
        hc = __bfloat16_as_ushort(hb); lc = __bfloat16_as_ushort(lb); }
    SPL(x, h.x, l.x) SPL(y, h.y, l.y) SPL(z, h.z, l.z) SPL(w, h.w, l.w)
#undef SPL
    hi[i] = h; lo[i] = l;
}

// ---------------------------------------------------------------------------
// Tensor-core GEMM (bf16x3): out[m,n] = sum_k A[m,k]*W[n,k] (+bias)
// MODE 0: A=g_xh/xl, B=g_wqh/wql, scatter QKV.  MODE 1: A=g_ah/al, B=g_woh/wol.
// CTA 128x128x32, 8 warps, warp tile 64x32, ldmatrix fragments,
// row-major smem with 20-word (80B) row stride -> conflict-free.
// 3 MMA passes: Ah*Bh + Ah*Bl + Al*Bh.
// ---------------------------------------------------------------------------
template<int MODE>
__global__ __launch_bounds__(256)
void gemm_bf16(const float* __restrict__ bias, float* __restrict__ out)
{
    __shared__ unsigned sAh[128][20], sAl[128][20], sBh[128][20], sBl[128][20];

    const __nv_bfloat16* Ah_g = (MODE == 0) ? g_xh  : g_ah;
    const __nv_bfloat16* Al_g = (MODE == 0) ? g_xl  : g_al;
    const __nv_bfloat16* Bh_g = (MODE == 0) ? g_wqh : g_woh;
    const __nv_bfloat16* Bl_g = (MODE == 0) ? g_wql : g_wol;

    const int tid  = threadIdx.x;
    const int warp = tid >> 5;
    const int lane = tid & 31;
    const int g = lane >> 2;
    const int t = lane & 3;
    const int wm = (warp & 1) * 64;
    const int wn = (warp >> 1) * 32;
    const int m0 = blockIdx.y * 128;
    const int n0 = blockIdx.x * 128;

    const int lrow = tid >> 1;
    const int loff = (tid & 1) * 8;

    const __nv_bfloat16* Ap  = Ah_g + (size_t)(m0 + lrow) * CC + loff * 2;
    const __nv_bfloat16* Alp = Al_g + (size_t)(m0 + lrow) * CC + loff * 2;
    const __nv_bfloat16* Bp  = Bh_g + (size_t)(n0 + lrow) * CC + loff * 2;
    const __nv_bfloat16* Blp = Bl_g + (size_t)(n0 + lrow) * CC + loff * 2;

    const unsigned aOff = (unsigned)(wm + (lane & 15)) * 80u + (unsigned)(lane >> 4) * 16u;
    const unsigned bOff = (unsigned)(wn + (lane & 7))  * 80u + (unsigned)((lane >> 3) & 1) * 16u;
    const unsigned baseAh = smem_u32(sAh) + aOff;
    const unsigned baseAl = smem_u32(sAl) + aOff;
    const unsigned baseBh = smem_u32(sBh) + bOff;
    const unsigned baseBl = smem_u32(sBl) + bOff;

    float acc[4][4][4];
    #pragma unroll
    for (int i = 0; i < 4; ++i)
        #pragma unroll
        for (int j = 0; j < 4; ++j)
            #pragma unroll
            for (int e = 0; e < 4; ++e) acc[i][j][e] = 0.f;

    uint4 rah0, rah1, ral0, ral1, rbh0, rbh1, rbl0, rbl1;
#define LOAD_STAGE(kt) { \
        const int eo = (kt) * 32; \
        rah0 = *(const uint4*)(Ap  + eo); rah1 = *(const uint4*)(Ap  + eo + 8); \
        ral0 = *(const uint4*)(Alp + eo); ral1 = *(const uint4*)(Alp + eo + 8); \
        rbh0 = *(const uint4*)(Bp  + eo); rbh1 = *(const uint4*)(Bp  + eo + 8); \
        rbl0 = *(const uint4*)(Blp + eo); rbl1 = *(const uint4*)(Blp + eo + 8); }

    LOAD_STAGE(0);

    #pragma unroll 1
    for (int kt = 0; kt < 32; ++kt) {
        *(uint4*)&sAh[lrow][loff]     = rah0; *(uint4*)&sAh[lrow][loff + 4] = rah1;
        *(uint4*)&sAl[lrow][loff]     = ral0; *(uint4*)&sAl[lrow][loff + 4] = ral1;
        *(uint4*)&sBh[lrow][loff]     = rbh0; *(uint4*)&sBh[lrow][loff + 4] = rbh1;
        *(uint4*)&sBl[lrow][loff]     = rbl0; *(uint4*)&sBl[lrow][loff + 4] = rbl1;
        __syncthreads();

        if (kt + 1 < 32) LOAD_STAGE(kt + 1);

        #pragma unroll
        for (int ks = 0; ks < 2; ++ks) {
            const unsigned ko = (unsigned)ks * 32u;   // 8 words = 16 bf16

            unsigned ah[4][4], al[4][4], bh[4][2], bl[4][2];
            #pragma unroll
            for (int mt = 0; mt < 4; ++mt) {
                LDSM_X4(ah[mt], baseAh + (unsigned)mt * 1280u + ko);
                LDSM_X4(al[mt], baseAl + (unsigned)mt * 1280u + ko);
            }
            #pragma unroll
            for (int nt = 0; nt < 4; ++nt) {
                LDSM_X2(bh[nt], baseBh + (unsigned)nt * 640u + ko);
                LDSM_X2(bl[nt], baseBl + (unsigned)nt * 640u + ko);
            }
            #pragma unroll
            for (int mt = 0; mt < 4; ++mt)
                #pragma unroll
                for (int nt = 0; nt < 4; ++nt) {
                    MMA_BF16(acc[mt][nt], ah[mt], bh[nt]);
                    MMA_BF16(acc[mt][nt], ah[mt], bl[nt]);
                    MMA_BF16(acc[mt][nt], al[mt], bh[nt]);
                }
        }
        __syncthreads();
    }

    // epilogue (standard m16n8 C fragment layout)
    #pragma unroll
    for (int mt = 0; mt < 4; ++mt)
        #pragma unroll
        for (int nt = 0; nt < 4; ++nt)
            #pragma unroll
            for (int i = 0; i < 4; ++i) {
                const int m = m0 + wm + mt * 16 + g + (i >> 1) * 8;
                const int n = n0 + wn + nt * 8 + t * 2 + (i & 1);
                float v = acc[mt][nt][i] + bias[n];
                if (MODE == 0) {
                    const int which = n >> 10;          // 0=q 1=k 2=v
                    const int hc = n & 1023;
                    const int h  = hc >> 6;
                    const int d  = hc & 63;
                    const int b  = m >> 11;
                    const int tt = m & (TT - 1);
                    float* dst = (which == 0) ? g_Q : (which == 1) ? g_K : g_V;
                    if (which == 0) v *= 0.125f;        // 1/sqrt(64)
                    dst[(size_t)((b*HH + h)*TT + tt) * HD + d] = v;
                } else {
                    out[(size_t)m * CC + n] = v;
                }
            }
}

// ---------------------------------------------------------------------------
// Causal flash attention (unchanged — fp32 FFMA2, proven correct in R4)
// ---------------------------------------------------------------------------
__global__ __launch_bounds__(128)
void attn_kernel()
{
    __shared__ __align__(16) float sQt[64][64];
    __shared__ __align__(16) float sKV[64][64];
    __shared__ __align__(16) float sP [64][64];

    const int tid = threadIdx.x;
    const int tx  = tid & 15;
    const int ty  = tid >> 4;
    const int tx4 = tx * 4, ty4 = ty * 4;
    const int q0 = blockIdx.x * 64;
    const int bh = blockIdx.y;

    const float* Qb = g_Q + (size_t)bh * TT * HD;
    const float* Kb = g_K + (size_t)bh * TT * HD;
    const float* Vb = g_V + (size_t)bh * TT * HD;

    int rIdx[8];
    #pragma unroll
    for (int i = 0; i < 8; ++i) rIdx[i] = (i < 4) ? ty4 + i : 32 + ty4 + (i - 4);

    {
        const int r = tid >> 1;
        #pragma unroll
        for (int s = 0; s < 8; ++s) {
            const int d4 = ((tid & 1) + 2*s) * 4;
            float4 v = *(const float4*)&Qb[(size_t)(q0 + r) * HD + d4];
            sQt[d4+0][r]=v.x; sQt[d4+1][r]=v.y; sQt[d4+2][r]=v.z; sQt[d4+3][r]=v.w;
        }
    }

    float m_i[8], l_i[8];
    unsigned long long accp[8][2];
    #pragma unroll
    for (int i = 0; i < 8; ++i) {
        m_i[i] = -1e30f; l_i[i] = 0.f;
        accp[i][0] = 0ull; accp[i][1] = 0ull;
    }

    #pragma unroll 1
    for (int j0 = 0; j0 <= q0; j0 += 64) {
        __syncthreads();
        {
            const int c = tid >> 1;
            #pragma unroll
            for (int s = 0; s < 8; ++s) {
                const int d4 = ((tid & 1) + 2*s) * 4;
                float4 v = *(const float4*)&Kb[(size_t)(j0 + c) * HD + d4];
                sKV[d4+0][c]=v.x; sKV[d4+1][c]=v.y; sKV[d4+2][c]=v.z; sKV[d4+3][c]=v.w;
            }
        }
        __syncthreads();

        unsigned long long sp[8][2];
        #pragma unroll
        for (int i = 0; i < 8; ++i) { sp[i][0] = 0ull; sp[i][1] = 0ull; }
        #pragma unroll 4
        for (int d = 0; d < 64; ++d) {
            float4 a0 = *(const float4*)&sQt[d][ty4];
            float4 a1 = *(const float4*)&sQt[d][32 + ty4];
            ulonglong2 b = *(const ulonglong2*)&sKV[d][tx4];
            float as[8] = {a0.x, a0.y, a0.z, a0.w, a1.x, a1.y, a1.z, a1.w};
            #pragma unroll
            for (int i = 0; i < 8; ++i) {
                unsigned long long ap;
                PACK2(ap, as[i]);
                FMA2(sp[i][0], ap, b.x);
                FMA2(sp[i][1], ap, b.y);
            }
        }
        float sf[8][4];
        #pragma unroll
        for (int i = 0; i < 8; ++i) {
            UNPK(sf[i][0], sf[i][1], sp[i][0]);
            UNPK(sf[i][2], sf[i][3], sp[i][1]);
        }

        if (j0 + 63 > q0) {
            #pragma unroll
            for (int i = 0; i < 8; ++i) {
                const int rg = q0 + rIdx[i];
                #pragma unroll
                for (int j = 0; j < 4; ++j)
                    if (j0 + tx4 + j > rg) sf[i][j] = -1e30f;
            }
        }

        #pragma unroll
        for (int i = 0; i < 8; ++i) {
            float tm = fmaxf(fmaxf(sf[i][0], sf[i][1]), fmaxf(sf[i][2], sf[i][3]));
            #pragma unroll
            for (int off = 8; off > 0; off >>= 1)
                tm = fmaxf(tm, __shfl_xor_sync(0xffffffffu, tm, off));
            const float mnew = fmaxf(m_i[i], tm);
            const float corr = __expf(m_i[i] - mnew);
            float4 pv;
            pv.x = __expf(sf[i][0] - mnew);
            pv.y = __expf(sf[i][1] - mnew);
            pv.z = __expf(sf[i][2] - mnew);
            pv.w = __expf(sf[i][3] - mnew);
            *(float4*)&sP[rIdx[i]][tx4] = pv;
            float ls = pv.x + pv.y + pv.z + pv.w;
            #pragma unroll
            for (int off = 8; off > 0; off >>= 1)
                ls += __shfl_xor_sync(0xffffffffu, ls, off);
            l_i[i] = l_i[i] * corr + ls;
            m_i[i] = mnew;
            unsigned long long cp;
            PACK2(cp, corr);
            MUL2(accp[i][0], cp);
            MUL2(accp[i][1], cp);
        }
        __syncthreads();

        #pragma unroll
        for (int s = 0; s < 8; ++s) {
            const int f = tid + s * 128;
            const int r = f >> 4, c4 = (f & 15) * 4;
            *(float4*)&sKV[r][c4] = *(const float4*)&Vb[(size_t)(j0 + r) * HD + c4];
        }
        __syncthreads();

        #pragma unroll 4
        for (int k = 0; k < 64; ++k) {
            ulonglong2 v = *(const ulonglong2*)&sKV[k][tx4];
            #pragma unroll
            for (int i = 0; i < 8; ++i) {
                unsigned long long pp;
                PACK2(pp, sP[rIdx[i]][k]);
                FMA2(accp[i][0], pp, v.x);
                FMA2(accp[i][1], pp, v.y);
            }
        }
    }

    const int b = bh >> 4;
    const int h = bh & 15;
    #pragma unroll
    for (int i = 0; i < 8; ++i) {
        const float inv = 1.f / l_i[i];
        const int t = q0 + rIdx[i];
        float4 o;
        UNPK(o.x, o.y, accp[i][0]);
        UNPK(o.z, o.w, accp[i][1]);
        o.x *= inv; o.y *= inv; o.z *= inv; o.w *= inv;
        *(float4*)&g_attn[(size_t)(b*TT + t) * CC + h*HD + tx4] = o;
    }
}

// ---------------------------------------------------------------------------
extern "C" void kernel_launch(void* const* d_in, const int* in_sizes, int n_in,
                              void* d_out, int out_size)
{
    const float* x     = (const float*)d_in[0];
    const float* qkv_w = (const float*)d_in[1];
    const float* qkv_b = (const float*)d_in[2];
    const float* out_w = (const float*)d_in[3];
    const float* out_b = (const float*)d_in[4];
    float* y = (float*)d_out;

    // bf16 hi/lo splits (destinations bound inside device code)
    {
        int n4 = MM*CC/4;
        split_kernel<0><<<(n4+255)/256, 256>>>((const float4*)x, n4);
    }
    {
        int n4 = 3*CC*CC/4;
        split_kernel<1><<<(n4+255)/256, 256>>>((const float4*)qkv_w, n4);
    }
    {
        int n4 = CC*CC/4;
        split_kernel<2><<<(n4+255)/256, 256>>>((const float4*)out_w, n4);
    }

    // 1) QKV projection (tensor cores) -> g_Q/g_K/g_V
    gemm_bf16<0><<<dim3(3*CC/128, MM/128), 256>>>(qkv_b, nullptr);
    // 2) causal attention (fp32)
    attn_kernel<<<dim3(TT/64, BB*HH), 128>>>();
    // 3) split attention output, then out-projection (tensor cores)
    {
        int n4 = MM*CC/4;
        split_kernel<3><<<(n4+255)/256, 256>>>(nullptr, n4);
    }
    gemm_bf16<1><<<dim3(CC/128, MM/128), 256>>>(out_b, y);
}

// round 11
// speedup vs baseline: 2.0799x; 1.4373x over previous
#include <cuda_runtime.h>
#include <cuda_bf16.h>
#include <cstdint>
#include <math.h>

#define BB 4
#define TT 2048
#define CC 1024
#define HH 16
#define HD 64
#define MM (BB*TT)
#define QS 72   // smem row stride in bf16 (144B): LDSM-conflict-free

// ---------------- scratch (static device arrays; no cudaMalloc) -------------
__device__ __nv_bfloat16 g_Qh[BB*HH*TT*HD], g_Ql[BB*HH*TT*HD];
__device__ __nv_bfloat16 g_Kh[BB*HH*TT*HD], g_Kl[BB*HH*TT*HD];
__device__ __nv_bfloat16 g_Vh[BB*HH*TT*HD], g_Vl[BB*HH*TT*HD];

__device__ __nv_bfloat16 g_xh[MM*CC],     g_xl[MM*CC];
__device__ __nv_bfloat16 g_wqh[3*CC*CC],  g_wql[3*CC*CC];
__device__ __nv_bfloat16 g_woh[CC*CC],    g_wol[CC*CC];
__device__ __nv_bfloat16 g_ah[MM*CC],     g_al[MM*CC];

// bf16 mma: D(f32) += A(bf16) * B(bf16)  (args fully parenthesized!)
#define MMA_BF16(acc, a, b) \
    asm("mma.sync.aligned.m16n8k16.row.col.f32.bf16.bf16.f32 " \
        "{%0,%1,%2,%3}, {%4,%5,%6,%7}, {%8,%9}, {%0,%1,%2,%3};" \
        : "+f"((acc)[0]), "+f"((acc)[1]), "+f"((acc)[2]), "+f"((acc)[3]) \
        : "r"((a)[0]), "r"((a)[1]), "r"((a)[2]), "r"((a)[3]), "r"((b)[0]), "r"((b)[1]))

#define LDSM_X4(r, addr) \
    asm volatile("ldmatrix.sync.aligned.m8n8.x4.shared.b16 {%0,%1,%2,%3}, [%4];" \
        : "=r"((r)[0]), "=r"((r)[1]), "=r"((r)[2]), "=r"((r)[3]) : "r"(addr))
#define LDSM_X2(r, addr) \
    asm volatile("ldmatrix.sync.aligned.m8n8.x2.shared.b16 {%0,%1}, [%2];" \
        : "=r"((r)[0]), "=r"((r)[1]) : "r"(addr))
#define LDSM_X4_T(r, addr) \
    asm volatile("ldmatrix.sync.aligned.m8n8.x4.trans.shared.b16 {%0,%1,%2,%3}, [%4];" \
        : "=r"((r)[0]), "=r"((r)[1]), "=r"((r)[2]), "=r"((r)[3]) : "r"(addr))

__device__ __forceinline__ unsigned smem_u32(const void* p) {
    return (unsigned)__cvta_generic_to_shared(p);
}
__device__ __forceinline__ unsigned pack_bf(__nv_bfloat16 lo, __nv_bfloat16 hi) {
    return ((unsigned)__bfloat16_as_ushort(hi) << 16) | __bfloat16_as_ushort(lo);
}

// ---------------------------------------------------------------------------
// split: fp32 -> (hi, lo) bf16. DST bound in device code. 0=x 1=qkv_w 2=out_w
// ---------------------------------------------------------------------------
template<int DST>
__global__ __launch_bounds__(256)
void split_kernel(const float4* __restrict__ src, int n4)
{
    int i = blockIdx.x * blockDim.x + threadIdx.x;
    if (i >= n4) return;
    ushort4* hi; ushort4* lo;
    if      (DST == 0) { hi = (ushort4*)g_xh;  lo = (ushort4*)g_xl;  }
    else if (DST == 1) { hi = (ushort4*)g_wqh; lo = (ushort4*)g_wql; }
    else               { hi = (ushort4*)g_woh; lo = (ushort4*)g_wol; }
    float4 v = src[i];
    ushort4 h, l;
#define SPL(c, hc, lc) { \
        __nv_bfloat16 hb = __float2bfloat16_rn(v.c); \
        __nv_bfloat16 lb = __float2bfloat16_rn(v.c - __bfloat162float(hb)); \
        hc = __bfloat16_as_ushort(hb); lc = __bfloat16_as_ushort(lb); }
    SPL(x, h.x, l.x) SPL(y, h.y, l.y) SPL(z, h.z, l.z) SPL(w, h.w, l.w)
#undef SPL
    hi[i] = h; lo[i] = l;
}

// ---------------------------------------------------------------------------
// Tensor-core GEMM (bf16x3): unchanged core from R9 (passing).
// MODE 0: QKV projection -> writes Q/K/V as bf16 hi/lo (split in epilogue).
// MODE 1: out-projection  -> writes fp32 d_out.
// ---------------------------------------------------------------------------
template<int MODE>
__global__ __launch_bounds__(256)
void gemm_bf16(const float* __restrict__ bias, float* __restrict__ out)
{
    __shared__ unsigned sAh[128][20], sAl[128][20], sBh[128][20], sBl[128][20];

    const __nv_bfloat16* Ah_g = (MODE == 0) ? g_xh  : g_ah;
    const __nv_bfloat16* Al_g = (MODE == 0) ? g_xl  : g_al;
    const __nv_bfloat16* Bh_g = (MODE == 0) ? g_wqh : g_woh;
    const __nv_bfloat16* Bl_g = (MODE == 0) ? g_wql : g_wol;

    const int tid  = threadIdx.x;
    const int warp = tid >> 5;
    const int lane = tid & 31;
    const int g = lane >> 2;
    const int t = lane & 3;
    const int wm = (warp & 1) * 64;
    const int wn = (warp >> 1) * 32;
    const int m0 = blockIdx.y * 128;
    const int n0 = blockIdx.x * 128;

    const int lrow = tid >> 1;
    const int loff = (tid & 1) * 8;

    const __nv_bfloat16* Ap  = Ah_g + (size_t)(m0 + lrow) * CC + loff * 2;
    const __nv_bfloat16* Alp = Al_g + (size_t)(m0 + lrow) * CC + loff * 2;
    const __nv_bfloat16* Bp  = Bh_g + (size_t)(n0 + lrow) * CC + loff * 2;
    const __nv_bfloat16* Blp = Bl_g + (size_t)(n0 + lrow) * CC + loff * 2;

    const unsigned aOff = (unsigned)(wm + (lane & 15)) * 80u + (unsigned)(lane >> 4) * 16u;
    const unsigned bOff = (unsigned)(wn + (lane & 7))  * 80u + (unsigned)((lane >> 3) & 1) * 16u;
    const unsigned baseAh = smem_u32(sAh) + aOff;
    const unsigned baseAl = smem_u32(sAl) + aOff;
    const unsigned baseBh = smem_u32(sBh) + bOff;
    const unsigned baseBl = smem_u32(sBl) + bOff;

    float acc[4][4][4];
    #pragma unroll
    for (int i = 0; i < 4; ++i)
        #pragma unroll
        for (int j = 0; j < 4; ++j)
            #pragma unroll
            for (int e = 0; e < 4; ++e) acc[i][j][e] = 0.f;

    uint4 rah0, rah1, ral0, ral1, rbh0, rbh1, rbl0, rbl1;
#define LOAD_STAGE(kt) { \
        const int eo = (kt) * 32; \
        rah0 = *(const uint4*)(Ap  + eo); rah1 = *(const uint4*)(Ap  + eo + 8); \
        ral0 = *(const uint4*)(Alp + eo); ral1 = *(const uint4*)(Alp + eo + 8); \
        rbh0 = *(const uint4*)(Bp  + eo); rbh1 = *(const uint4*)(Bp  + eo + 8); \
        rbl0 = *(const uint4*)(Blp + eo); rbl1 = *(const uint4*)(Blp + eo + 8); }

    LOAD_STAGE(0);

    #pragma unroll 1
    for (int kt = 0; kt < 32; ++kt) {
        *(uint4*)&sAh[lrow][loff]     = rah0; *(uint4*)&sAh[lrow][loff + 4] = rah1;
        *(uint4*)&sAl[lrow][loff]     = ral0; *(uint4*)&sAl[lrow][loff + 4] = ral1;
        *(uint4*)&sBh[lrow][loff]     = rbh0; *(uint4*)&sBh[lrow][loff + 4] = rbh1;
        *(uint4*)&sBl[lrow][loff]     = rbl0; *(uint4*)&sBl[lrow][loff + 4] = rbl1;
        __syncthreads();

        if (kt + 1 < 32) LOAD_STAGE(kt + 1);

        #pragma unroll
        for (int ks = 0; ks < 2; ++ks) {
            const unsigned ko = (unsigned)ks * 32u;

            unsigned ah[4][4], al[4][4], bh[4][2], bl[4][2];
            #pragma unroll
            for (int mt = 0; mt < 4; ++mt) {
                LDSM_X4(ah[mt], baseAh + (unsigned)mt * 1280u + ko);
                LDSM_X4(al[mt], baseAl + (unsigned)mt * 1280u + ko);
            }
            #pragma unroll
            for (int nt = 0; nt < 4; ++nt) {
                LDSM_X2(bh[nt], baseBh + (unsigned)nt * 640u + ko);
                LDSM_X2(bl[nt], baseBl + (unsigned)nt * 640u + ko);
            }
            #pragma unroll
            for (int mt = 0; mt < 4; ++mt)
                #pragma unroll
                for (int nt = 0; nt < 4; ++nt) {
                    MMA_BF16(acc[mt][nt], ah[mt], bh[nt]);
                    MMA_BF16(acc[mt][nt], ah[mt], bl[nt]);
                    MMA_BF16(acc[mt][nt], al[mt], bh[nt]);
                }
        }
        __syncthreads();
    }

    #pragma unroll
    for (int mt = 0; mt < 4; ++mt)
        #pragma unroll
        for (int nt = 0; nt < 4; ++nt)
            #pragma unroll
            for (int i = 0; i < 4; ++i) {
                const int m = m0 + wm + mt * 16 + g + (i >> 1) * 8;
                const int n = n0 + wn + nt * 8 + t * 2 + (i & 1);
                float v = acc[mt][nt][i] + bias[n];
                if (MODE == 0) {
                    const int which = n >> 10;          // 0=q 1=k 2=v
                    const int hc = n & 1023;
                    const int h  = hc >> 6;
                    const int d  = hc & 63;
                    const int b  = m >> 11;
                    const int tt = m & (TT - 1);
                    __nv_bfloat16* dh = (which == 0) ? g_Qh : (which == 1) ? g_Kh : g_Vh;
                    __nv_bfloat16* dl = (which == 0) ? g_Ql : (which == 1) ? g_Kl : g_Vl;
                    if (which == 0) v *= 0.125f;        // 1/sqrt(64)
                    __nv_bfloat16 hb = __float2bfloat16_rn(v);
                    __nv_bfloat16 lb = __float2bfloat16_rn(v - __bfloat162float(hb));
                    const size_t off = (size_t)((b*HH + h)*TT + tt) * HD + d;
                    dh[off] = hb; dl[off] = lb;
                } else {
                    out[(size_t)m * CC + n] = v;
                }
            }
}

// ---------------------------------------------------------------------------
// Tensor-core causal flash attention (bf16x3).
// CTA: 128 thr (4 warps), 64 q-rows (warp = m16), 64-key tiles.
// S = Qh*Kh + Qh*Kl + Ql*Kh; PV = Ph*Vh + Ph*Vl + Pl*Vh (P split in regs).
// Writes g_ah/g_al (bf16 hi/lo of attention output) directly.
// ---------------------------------------------------------------------------
__global__ __launch_bounds__(128)
void attn_mma()
{
    __shared__ __align__(16) __nv_bfloat16 sQh[64*QS], sQl[64*QS];
    __shared__ __align__(16) __nv_bfloat16 sKVh[64*QS], sKVl[64*QS];

    const int tid  = threadIdx.x;
    const int warp = tid >> 5;
    const int lane = tid & 31;
    const int g = lane >> 2;
    const int t = lane & 3;
    const int q0 = blockIdx.x * 64;
    const int bh = blockIdx.y;
    const size_t gbase = (size_t)bh * TT * HD;

    // Q tile -> smem (rows q0..q0+63)
    #pragma unroll
    for (int idx = tid; idx < 512; idx += 128) {
        const int r = idx >> 3, c = idx & 7;
        const size_t go = gbase + (size_t)(q0 + r) * HD + c * 8;
        *(uint4*)&sQh[r*QS + c*8] = *(const uint4*)&g_Qh[go];
        *(uint4*)&sQl[r*QS + c*8] = *(const uint4*)&g_Ql[go];
    }

    // per-lane LDSM byte offsets (row stride 144B)
    const unsigned qOff = (unsigned)(warp*16 + (lane & 15)) * 144u + (unsigned)(lane >> 4) * 16u;
    const unsigned kOff = (unsigned)(((lane >> 4) & 1) * 8 + (lane & 7)) * 144u
                        + (unsigned)((lane >> 3) & 1) * 16u;
    const unsigned vOff = (unsigned)(((lane >> 3) & 1) * 8 + (lane & 7)) * 144u
                        + (unsigned)((lane >> 4) & 1) * 16u;
    const unsigned qbh = smem_u32(sQh)  + qOff, qbl = smem_u32(sQl)  + qOff;
    const unsigned kbh = smem_u32(sKVh) + kOff, kbl = smem_u32(sKVl) + kOff;
    const unsigned vbh = smem_u32(sKVh) + vOff, vbl = smem_u32(sKVl) + vOff;

    float m_i[2] = {-1e30f, -1e30f}, l_i[2] = {0.f, 0.f};
    float oacc[8][4];
    #pragma unroll
    for (int i = 0; i < 8; ++i)
        #pragma unroll
        for (int e = 0; e < 4; ++e) oacc[i][e] = 0.f;

    #pragma unroll 1
    for (int j0 = 0; j0 <= q0; j0 += 64) {
        // ---- K tile ----
        __syncthreads();   // prior V reads done
        #pragma unroll
        for (int idx = tid; idx < 512; idx += 128) {
            const int r = idx >> 3, c = idx & 7;
            const size_t go = gbase + (size_t)(j0 + r) * HD + c * 8;
            *(uint4*)&sKVh[r*QS + c*8] = *(const uint4*)&g_Kh[go];
            *(uint4*)&sKVl[r*QS + c*8] = *(const uint4*)&g_Kl[go];
        }
        __syncthreads();

        // ---- S = Q K^T ----
        float sacc[8][4];
        #pragma unroll
        for (int i = 0; i < 8; ++i)
            #pragma unroll
            for (int e = 0; e < 4; ++e) sacc[i][e] = 0.f;

        #pragma unroll
        for (int kc = 0; kc < 4; ++kc) {
            unsigned qh[4], ql[4];
            LDSM_X4(qh, qbh + kc*32u);
            LDSM_X4(ql, qbl + kc*32u);
            #pragma unroll
            for (int ntp = 0; ntp < 4; ++ntp) {
                unsigned kh[4], kl[4];
                LDSM_X4(kh, kbh + (unsigned)ntp*2304u + kc*32u);
                LDSM_X4(kl, kbl + (unsigned)ntp*2304u + kc*32u);
                MMA_BF16(sacc[2*ntp],   qh, kh);
                MMA_BF16(sacc[2*ntp],   qh, kl);
                MMA_BF16(sacc[2*ntp],   ql, kh);
                MMA_BF16(sacc[2*ntp+1], qh, kh + 2);
                MMA_BF16(sacc[2*ntp+1], qh, kl + 2);
                MMA_BF16(sacc[2*ntp+1], ql, kh + 2);
            }
        }

        // ---- causal mask (only diagonal tile) ----
        if (j0 == q0) {
            const int rbase = q0 + warp*16;
            #pragma unroll
            for (int nt = 0; nt < 8; ++nt)
                #pragma unroll
                for (int e = 0; e < 4; ++e) {
                    const int col = j0 + nt*8 + t*2 + (e & 1);
                    const int row = rbase + g + (e >> 1)*8;
                    if (col > row) sacc[nt][e] = -1e30f;
                }
        }

        // ---- online softmax (rows g and g+8) ----
        #pragma unroll
        for (int h2 = 0; h2 < 2; ++h2) {
            float mloc = -1e30f;
            #pragma unroll
            for (int nt = 0; nt < 8; ++nt)
                mloc = fmaxf(mloc, fmaxf(sacc[nt][2*h2], sacc[nt][2*h2+1]));
            mloc = fmaxf(mloc, __shfl_xor_sync(0xffffffffu, mloc, 1));
            mloc = fmaxf(mloc, __shfl_xor_sync(0xffffffffu, mloc, 2));
            const float mnew = fmaxf(m_i[h2], mloc);
            const float corr = __expf(m_i[h2] - mnew);
            float sum = 0.f;
            #pragma unroll
            for (int nt = 0; nt < 8; ++nt) {
                const float p0 = __expf(sacc[nt][2*h2]   - mnew);
                const float p1 = __expf(sacc[nt][2*h2+1] - mnew);
                sacc[nt][2*h2] = p0; sacc[nt][2*h2+1] = p1;
                sum += p0 + p1;
            }
            sum += __shfl_xor_sync(0xffffffffu, sum, 1);
            sum += __shfl_xor_sync(0xffffffffu, sum, 2);
            l_i[h2] = l_i[h2] * corr + sum;
            m_i[h2] = mnew;
            #pragma unroll
            for (int dt = 0; dt < 8; ++dt) {
                oacc[dt][2*h2] *= corr; oacc[dt][2*h2+1] *= corr;
            }
        }

        // ---- V tile (reuse KV buffer) ----
        __syncthreads();   // S fragment loads done
        #pragma unroll
        for (int idx = tid; idx < 512; idx += 128) {
            const int r = idx >> 3, c = idx & 7;
            const size_t go = gbase + (size_t)(j0 + r) * HD + c * 8;
            *(uint4*)&sKVh[r*QS + c*8] = *(const uint4*)&g_Vh[go];
            *(uint4*)&sKVl[r*QS + c*8] = *(const uint4*)&g_Vl[go];
        }
        __syncthreads();

        // ---- O += P V ----
        #pragma unroll
        for (int kc = 0; kc < 4; ++kc) {
            // P fragments from sacc tiles 2kc, 2kc+1 (C layout == A layout)
            unsigned ph[4], pl[4];
            #pragma unroll
            for (int u = 0; u < 4; ++u) {
                const int nt = 2*kc + (u >> 1);
                const float a0 = sacc[nt][(u & 1)*2], a1 = sacc[nt][(u & 1)*2 + 1];
                const __nv_bfloat16 h0 = __float2bfloat16_rn(a0);
                const __nv_bfloat16 h1 = __float2bfloat16_rn(a1);
                ph[u] = pack_bf(h0, h1);
                pl[u] = pack_bf(__float2bfloat16_rn(a0 - __bfloat162float(h0)),
                                __float2bfloat16_rn(a1 - __bfloat162float(h1)));
            }
            #pragma unroll
            for (int dtp = 0; dtp < 4; ++dtp) {
                unsigned vh[4], vl[4];
                LDSM_X4_T(vh, vbh + (unsigned)kc*2304u + dtp*32u);
                LDSM_X4_T(vl, vbl + (unsigned)kc*2304u + dtp*32u);
                MMA_BF16(oacc[2*dtp],   ph, vh);
                MMA_BF16(oacc[2*dtp],   ph, vl);
                MMA_BF16(oacc[2*dtp],   pl, vh);
                MMA_BF16(oacc[2*dtp+1], ph, vh + 2);
                MMA_BF16(oacc[2*dtp+1], ph, vl + 2);
                MMA_BF16(oacc[2*dtp+1], pl, vh + 2);
            }
        }
    }

    // ---- epilogue: normalize, split to bf16 h/l, merge heads ----
    const int b  = bh >> 4;
    const int hh = bh & 15;
    #pragma unroll
    for (int h2 = 0; h2 < 2; ++h2) {
        const float inv = 1.f / l_i[h2];
        const int r = q0 + warp*16 + g + h2*8;
        const size_t rowoff = (size_t)(b*TT + r) * CC + hh*HD;
        #pragma unroll
        for (int dt = 0; dt < 8; ++dt) {
            const float o0 = oacc[dt][2*h2] * inv;
            const float o1 = oacc[dt][2*h2+1] * inv;
            const __nv_bfloat16 h0 = __float2bfloat16_rn(o0);
            const __nv_bfloat16 h1 = __float2bfloat16_rn(o1);
            const unsigned wh = pack_bf(h0, h1);
            const unsigned wl = pack_bf(__float2bfloat16_rn(o0 - __bfloat162float(h0)),
                                        __float2bfloat16_rn(o1 - __bfloat162float(h1)));
            *(unsigned*)&g_ah[rowoff + dt*8 + t*2] = wh;
            *(unsigned*)&g_al[rowoff + dt*8 + t*2] = wl;
        }
    }
}

// ---------------------------------------------------------------------------
extern "C" void kernel_launch(void* const* d_in, const int* in_sizes, int n_in,
                              void* d_out, int out_size)
{
    const float* x     = (const float*)d_in[0];
    const float* qkv_b = (const float*)d_in[2];
    const float* out_b = (const float*)d_in[4];
    float* y = (float*)d_out;

    {
        int n4 = MM*CC/4;
        split_kernel<0><<<(n4+255)/256, 256>>>((const float4*)x, n4);
    }
    {
        int n4 = 3*CC*CC/4;
        split_kernel<1><<<(n4+255)/256, 256>>>((const float4*)d_in[1], n4);
    }
    {
        int n4 = CC*CC/4;
        split_kernel<2><<<(n4+255)/256, 256>>>((const float4*)d_in[3], n4);
    }

    // 1) QKV projection -> Q/K/V bf16 hi/lo
    gemm_bf16<0><<<dim3(3*CC/128, MM/128), 256>>>(qkv_b, nullptr);
    // 2) causal attention (tensor cores) -> g_ah/g_al
    attn_mma<<<dim3(TT/64, BB*HH), 128>>>();
    // 3) output projection
    gemm_bf16<1><<<dim3(CC/128, MM/128), 256>>>(out_b, y);
}